// round 8
// baseline (speedup 1.0000x reference)
#include <cuda_runtime.h>
#include <cstdint>

#define B_ 64
#define N_ 1024
#define F_ 128
#define H_ 256

// Scratch (allocation-free rule: __device__ globals)
__device__ float g_T1[B_ * N_ * F_];            // adj @ embs        [B,N,F]  (tf32-rounded)
__device__ float g_T2[(size_t)B_ * N_ * H_];    // (relu(T1@W0+b0)) @ W1   [B,N,H]
__device__ float g_hid2[(size_t)B_ * N_ * H_];  // relu(adj@T2+b1)   [B,N,H]

__device__ __forceinline__ uint32_t s2u(const void* p) {
    uint32_t a;
    asm("{ .reg .u64 t; cvta.to.shared.u64 t, %1; cvt.u32.u64 %0, t; }" : "=r"(a) : "l"(p));
    return a;
}
__device__ __forceinline__ uint32_t f2tf(float f) {
    uint32_t r;
    asm("cvt.rna.tf32.f32 %0, %1;" : "=r"(r) : "f"(f));
    return r;
}
__device__ __forceinline__ uint32_t cvt_inplace(uint32_t x) {
    uint32_t r;
    asm("cvt.rna.tf32.f32 %0, %1;" : "=r"(r) : "f"(__uint_as_float(x)));
    return r;
}
__device__ __forceinline__ void ldsm4(uint32_t* r, uint32_t addr) {
    asm volatile("ldmatrix.sync.aligned.m8n8.x4.shared.b16 {%0,%1,%2,%3}, [%4];"
                 : "=r"(r[0]), "=r"(r[1]), "=r"(r[2]), "=r"(r[3]) : "r"(addr));
}
__device__ __forceinline__ void mma_tf32(float* d, const uint32_t* a, const uint32_t* b) {
    asm volatile(
        "mma.sync.aligned.m16n8k8.row.col.f32.tf32.tf32.f32 "
        "{%0,%1,%2,%3}, {%4,%5,%6,%7}, {%8,%9}, {%0,%1,%2,%3};"
        : "+f"(d[0]), "+f"(d[1]), "+f"(d[2]), "+f"(d[3])
        : "r"(a[0]), "r"(a[1]), "r"(a[2]), "r"(a[3]), "r"(b[0]), "r"(b[1]));
}
__device__ __forceinline__ void cpasync16(uint32_t dst, const void* src) {
    asm volatile("cp.async.cg.shared.global [%0], [%1], 16;" :: "r"(dst), "l"(src));
}
__device__ __forceinline__ void cp_commit() { asm volatile("cp.async.commit_group;"); }

// ---------------------------------------------------------------------------
// R7 GEMM (proven): C[M,N] = A[M,K] @ B[K,N], CTA 128x128x32, 128 thr,
// 2x2 warps, warp 64x64, frag double-buffered, 3-stage cp.async A, 2-stage B.
// ---------------------------------------------------------------------------
template <int CVT_A, int PREROUND>
__global__ __launch_bounds__(128)
void gemm_mma(const float* __restrict__ Ag, const float* __restrict__ Bg,
              float* __restrict__ Cg, int K, int nk, int ldb,
              long sA, long sB, long sC,
              const float* __restrict__ bias, int relu)
{
    extern __shared__ float smp[];
    const uint32_t smb = s2u(smp);
    const int tid = threadIdx.x;
    const int lid = tid & 31;
    const int wid = tid >> 5;
    const int mw = wid >> 1;
    const int nw = wid & 1;

    const float* A = Ag + (size_t)blockIdx.z * sA + (size_t)blockIdx.y * 128 * K;
    const float* Bp = Bg + (size_t)blockIdx.z * sB + blockIdx.x * 128 + tid;
    float* C = Cg + (size_t)blockIdx.z * sC + (size_t)blockIdx.y * 128 * ldb + blockIdx.x * 128;
    if (bias) bias += blockIdx.x * 128;

    const int a_row_l = tid >> 3;
    const int a_f4 = tid & 7;
    auto issueA = [&](int kt, int st) {
        const uint32_t dstb = smb + st * 16384;
        const float* src = A + (size_t)kt * 32 + a_f4 * 4;
#pragma unroll
        for (int j = 0; j < 8; j++) {
            int row = a_row_l + j * 16;
            uint32_t dst = dstb + row * 128 + ((a_f4 ^ (row & 7)) << 4);
            cpasync16(dst, src + (size_t)row * K);
        }
        cp_commit();
    };

    float bv[32];
    auto ldgB = [&](int kt) {
        const float* src = Bp + (size_t)kt * 32 * ldb;
#pragma unroll
        for (int k = 0; k < 32; k++) bv[k] = src[(size_t)k * ldb];
    };
    const uint32_t b_row128 = tid * 128;
    const int b_n7 = tid & 7;
    auto stsB = [&](int st) {
        char* base = (char*)smp + 49152 + st * 16384 + b_row128;
#pragma unroll
        for (int k4 = 0; k4 < 8; k4++) {
            uint4 w;
            w.x = f2tf(bv[4 * k4 + 0]);
            w.y = f2tf(bv[4 * k4 + 1]);
            w.z = f2tf(bv[4 * k4 + 2]);
            w.w = f2tf(bv[4 * k4 + 3]);
            *(uint4*)(base + ((k4 ^ b_n7) << 4)) = w;
        }
    };

    int aR128[4], aR7[4];
    const int l4a = (lid >> 4) & 1;
#pragma unroll
    for (int mf = 0; mf < 4; mf++) {
        int r = mw * 64 + mf * 16 + (lid & 7) + 8 * ((lid >> 3) & 1);
        aR128[mf] = r * 128;
        aR7[mf] = r & 7;
    }
    int bN128[4], bN7[4];
    const int l4b = (lid >> 3) & 1;
#pragma unroll
    for (int p = 0; p < 4; p++) {
        int n = nw * 64 + p * 16 + (lid & 7) + 8 * ((lid >> 4) & 1);
        bN128[p] = n * 128;
        bN7[p] = n & 7;
    }

    float acc[4][8][4];
#pragma unroll
    for (int mf = 0; mf < 4; mf++)
#pragma unroll
        for (int nf = 0; nf < 8; nf++)
#pragma unroll
            for (int e = 0; e < 4; e++) acc[mf][nf][e] = 0.f;

    issueA(0, 0);
    issueA(1, 1);
    ldgB(0);
    stsB(0);
    asm volatile("cp.async.wait_group 1;");
    __syncthreads();

    int sa = 0;
    for (int t = 0; t < nk; t++) {
        if (t + 2 < nk) issueA(t + 2, (t + 2) % 3);
        if (t + 1 < nk) ldgB(t + 1);

        const uint32_t Ab = smb + sa * 16384;
        const uint32_t Bb = smb + 49152 + (t & 1) * 16384;

        uint32_t a[2][4][4], b[2][8][2];
        auto ldfr = [&](int kb, int pb) {
#pragma unroll
            for (int mf = 0; mf < 4; mf++) {
                ldsm4(a[pb][mf], Ab + aR128[mf] + ((((kb << 1) | l4a) ^ aR7[mf]) << 4));
                if (CVT_A) {
                    a[pb][mf][0] = cvt_inplace(a[pb][mf][0]);
                    a[pb][mf][1] = cvt_inplace(a[pb][mf][1]);
                    a[pb][mf][2] = cvt_inplace(a[pb][mf][2]);
                    a[pb][mf][3] = cvt_inplace(a[pb][mf][3]);
                }
            }
#pragma unroll
            for (int p = 0; p < 4; p++) {
                uint32_t r[4];
                ldsm4(r, Bb + bN128[p] + ((((kb << 1) | l4b) ^ bN7[p]) << 4));
                b[pb][2 * p][0] = r[0]; b[pb][2 * p][1] = r[1];
                b[pb][2 * p + 1][0] = r[2]; b[pb][2 * p + 1][1] = r[3];
            }
        };

        ldfr(0, 0);
#pragma unroll
        for (int kb = 0; kb < 4; kb++) {
            if (kb < 3) ldfr(kb + 1, (kb + 1) & 1);
            const int pb = kb & 1;
#pragma unroll
            for (int mf = 0; mf < 4; mf++)
#pragma unroll
                for (int nf = 0; nf < 8; nf++)
                    mma_tf32(acc[mf][nf], a[pb][mf], b[pb][nf]);
        }

        if (t + 1 < nk) {
            stsB((t + 1) & 1);
            if (t + 2 < nk) asm volatile("cp.async.wait_group 1;");
            else            asm volatile("cp.async.wait_group 0;");
        }
        __syncthreads();
        sa = (sa + 1 == 3) ? 0 : sa + 1;
    }

    const int r0 = mw * 64 + (lid >> 2);
    const int c0 = nw * 64 + (lid & 3) * 2;
#pragma unroll
    for (int mf = 0; mf < 4; mf++) {
        const int row = r0 + mf * 16;
#pragma unroll
        for (int nf = 0; nf < 8; nf++) {
            const int col = c0 + nf * 8;
            float2 v0 = make_float2(acc[mf][nf][0], acc[mf][nf][1]);
            float2 v1 = make_float2(acc[mf][nf][2], acc[mf][nf][3]);
            if (bias) {
                float bx = bias[col], by = bias[col + 1];
                v0.x += bx; v0.y += by; v1.x += bx; v1.y += by;
            }
            if (relu) {
                v0.x = fmaxf(v0.x, 0.f); v0.y = fmaxf(v0.y, 0.f);
                v1.x = fmaxf(v1.x, 0.f); v1.y = fmaxf(v1.y, 0.f);
            }
            if (PREROUND) {
                v0.x = __uint_as_float(f2tf(v0.x)); v0.y = __uint_as_float(f2tf(v0.y));
                v1.x = __uint_as_float(f2tf(v1.x)); v1.y = __uint_as_float(f2tf(v1.y));
            }
            *(float2*)(C + (size_t)row * ldb + col) = v0;
            *(float2*)(C + (size_t)(row + 8) * ldb + col) = v1;
        }
    }
}

// ---------------------------------------------------------------------------
// Fused mid kernel: T2 = (relu(T1 @ W0 + b0)) @ W1 for one 128-row tile.
// 256 threads, 8 warps (2m x 4n), warp tile 64x64, CTA output 128x256.
// Phase 1 (K=128): A = T1 tile (pre-rounded; LDG->STS 2-stage), B = W0.
//   Epilogue: bias+relu+tf32-round, written into SMEM hid1s laid out as
//   8 A-tiles (kt*16384 + row*128B, f4-XOR swizzle).
// Phase 2 (K=256): A = hid1s (ldsm direct from SMEM, no loads), B = W1.
// SMEM: hid1s[0,128K) | B stages [128K,192K) | A stages [192K,224K).
// ---------------------------------------------------------------------------
__global__ __launch_bounds__(256)
void mid_kernel(const float* __restrict__ T1, const float* __restrict__ W0,
                const float* __restrict__ b0, const float* __restrict__ W1,
                float* __restrict__ T2out)
{
    constexpr uint32_t BOFF = 131072, BSTG = 32768, AOFF = 196608;
    extern __shared__ float smp[];
    const uint32_t smb = s2u(smp);
    const int tid = threadIdx.x;
    const int lid = tid & 31;
    const int wid = tid >> 5;
    const int mw = wid >> 2;   // 0..1
    const int nw = wid & 3;    // 0..3

    const float* A = T1 + (size_t)blockIdx.x * 128 * 128;
    float* C = T2out + (size_t)blockIdx.x * 128 * 256;

    // ---- phase-1 A producer: 4 f4/thread, raw copy (T1 already tf32) ----
    float4 av[4];
    auto ldgA = [&](int kt) {
#pragma unroll
        for (int j = 0; j < 4; j++) {
            int f4 = tid + j * 256, row = f4 >> 3, c4 = f4 & 7;
            av[j] = *(const float4*)(A + (size_t)row * 128 + kt * 32 + c4 * 4);
        }
    };
    auto stsA = [&](int st) {
#pragma unroll
        for (int j = 0; j < 4; j++) {
            int f4 = tid + j * 256, row = f4 >> 3, c4 = f4 & 7;
            *(float4*)((char*)smp + AOFF + st * 16384 + row * 128 +
                       ((c4 ^ (row & 7)) << 4)) = av[j];
        }
    };

    // ---- B producer: thread owns n = tid (256 cols) ----
    float bv[32];
    auto ldgB = [&](const float* __restrict__ W, int kt) {
        const float* src = W + (size_t)kt * 32 * 256 + tid;
#pragma unroll
        for (int k = 0; k < 32; k++) bv[k] = src[(size_t)k * 256];
    };
    const int b_n7 = tid & 7;
    auto stsB = [&](int st) {
        char* base = (char*)smp + BOFF + st * BSTG + tid * 128;
#pragma unroll
        for (int k4 = 0; k4 < 8; k4++) {
            uint4 w;
            w.x = f2tf(bv[4 * k4 + 0]);
            w.y = f2tf(bv[4 * k4 + 1]);
            w.z = f2tf(bv[4 * k4 + 2]);
            w.w = f2tf(bv[4 * k4 + 3]);
            *(uint4*)(base + ((k4 ^ b_n7) << 4)) = w;
        }
    };

    // ---- frag addressing ----
    int aR128[4], aR7[4];
    const int l4a = (lid >> 4) & 1;
#pragma unroll
    for (int mf = 0; mf < 4; mf++) {
        int r = mw * 64 + mf * 16 + (lid & 7) + 8 * ((lid >> 3) & 1);
        aR128[mf] = r * 128;
        aR7[mf] = r & 7;
    }
    int bN128[4], bN7[4];
    const int l4b = (lid >> 3) & 1;
#pragma unroll
    for (int p = 0; p < 4; p++) {
        int n = nw * 64 + p * 16 + (lid & 7) + 8 * ((lid >> 4) & 1);
        bN128[p] = n * 128;
        bN7[p] = n & 7;
    }

    float acc[4][8][4];
    uint32_t a[2][4][4], b[2][8][2];
    auto ldfr = [&](uint32_t Ab, uint32_t Bb, int kb, int pb) {
#pragma unroll
        for (int mf = 0; mf < 4; mf++)
            ldsm4(a[pb][mf], Ab + aR128[mf] + ((((kb << 1) | l4a) ^ aR7[mf]) << 4));
#pragma unroll
        for (int p = 0; p < 4; p++) {
            uint32_t r[4];
            ldsm4(r, Bb + bN128[p] + ((((kb << 1) | l4b) ^ bN7[p]) << 4));
            b[pb][2 * p][0] = r[0]; b[pb][2 * p][1] = r[1];
            b[pb][2 * p + 1][0] = r[2]; b[pb][2 * p + 1][1] = r[3];
        }
    };
    auto mmas = [&](int pb) {
#pragma unroll
        for (int mf = 0; mf < 4; mf++)
#pragma unroll
            for (int nf = 0; nf < 8; nf++)
                mma_tf32(acc[mf][nf], a[pb][mf], b[pb][nf]);
    };
    auto zero_acc = [&]() {
#pragma unroll
        for (int mf = 0; mf < 4; mf++)
#pragma unroll
            for (int nf = 0; nf < 8; nf++)
#pragma unroll
                for (int e = 0; e < 4; e++) acc[mf][nf][e] = 0.f;
    };

    const int r0 = mw * 64 + (lid >> 2);
    const int c0 = nw * 64 + (lid & 3) * 2;

    // ================= phase 1: hid1 = relu(T1 @ W0 + b0) =================
    zero_acc();
    ldgA(0); ldgB(W0, 0);
    stsA(0); stsB(0);
    ldgA(1); ldgB(W0, 1);
    __syncthreads();

    for (int t = 0; t < 4; t++) {
        if (t + 1 < 4) { stsA((t + 1) & 1); stsB((t + 1) & 1); }
        if (t + 2 < 4) { ldgA(t + 2); ldgB(W0, t + 2); }
        const uint32_t Ab = smb + AOFF + (t & 1) * 16384;
        const uint32_t Bb = smb + BOFF + (t & 1) * BSTG;
        ldfr(Ab, Bb, 0, 0);
#pragma unroll
        for (int kb = 0; kb < 4; kb++) {
            if (kb < 3) ldfr(Ab, Bb, kb + 1, (kb + 1) & 1);
            mmas(kb & 1);
        }
        __syncthreads();
    }

    // epilogue 1: bias + relu + tf32 round -> hid1s (A-tile layout)
#pragma unroll
    for (int mf = 0; mf < 4; mf++) {
#pragma unroll
        for (int nf = 0; nf < 8; nf++) {
            const int col = c0 + nf * 8;
            const float bx = b0[col], by = b0[col + 1];
#pragma unroll
            for (int h = 0; h < 2; h++) {   // h=0: e0/e1 row, h=1: e2/e3 row+8
                const int row = r0 + mf * 16 + h * 8;
                uint2 w;
                w.x = f2tf(fmaxf(acc[mf][nf][2 * h + 0] + bx, 0.f));
                w.y = f2tf(fmaxf(acc[mf][nf][2 * h + 1] + by, 0.f));
                const int kt = col >> 5, kc = col & 31, cc4 = kc >> 2;
                *(uint2*)((char*)smp + kt * 16384 + row * 128 +
                          ((cc4 ^ (row & 7)) << 4) + (kc & 3) * 4) = w;
            }
        }
    }

    // ================= phase 2: T2 = hid1s @ W1 =================
    zero_acc();
    ldgB(W1, 0);
    stsB(0);              // B stage 0 free: phase-1 last consumed stage 1
    ldgB(W1, 1);
    __syncthreads();      // hid1s visible + B stage 0 ready

    for (int t = 0; t < 8; t++) {
        if (t + 1 < 8) stsB((t + 1) & 1);
        if (t + 2 < 8) ldgB(W1, t + 2);
        const uint32_t Ab = smb + t * 16384;  // hid1s tile kt = t
        const uint32_t Bb = smb + BOFF + (t & 1) * BSTG;
        ldfr(Ab, Bb, 0, 0);
#pragma unroll
        for (int kb = 0; kb < 4; kb++) {
            if (kb < 3) ldfr(Ab, Bb, kb + 1, (kb + 1) & 1);
            mmas(kb & 1);
        }
        __syncthreads();
    }

    // epilogue 2: plain store
#pragma unroll
    for (int mf = 0; mf < 4; mf++) {
        const int row = r0 + mf * 16;
#pragma unroll
        for (int nf = 0; nf < 8; nf++) {
            const int col = c0 + nf * 8;
            *(float2*)(C + (size_t)row * 256 + col) =
                make_float2(acc[mf][nf][0], acc[mf][nf][1]);
            *(float2*)(C + (size_t)(row + 8) * 256 + col) =
                make_float2(acc[mf][nf][2], acc[mf][nf][3]);
        }
    }
}

// ---------------- tail: layer2 sliced to node 0 + linear head ----------------
__global__ __launch_bounds__(1024)
void tail_kernel(const float* __restrict__ adj, const float* __restrict__ hid2,
                 const float* __restrict__ W2, const float* __restrict__ b2,
                 const float* __restrict__ Wl, const float* __restrict__ bl,
                 float* __restrict__ out)
{
    const int b = blockIdx.x;
    const int t = threadIdx.x;  // 1024
    __shared__ float arow[N_];
    __shared__ float part[4][H_];
    __shared__ float rs[H_];
    __shared__ float ss[H_];
    __shared__ float partl[8][F_];

    const float* ar = adj + (size_t)b * N_ * N_;
    arow[t] = ar[t];
    __syncthreads();

    {   // r = arow @ hid2   [H_]
        const float* h2 = hid2 + (size_t)b * N_ * H_;
        const int h = t & (H_ - 1);
        const int sec = t >> 8;
        float acc = 0.f;
        const int n0 = sec * 256;
#pragma unroll 4
        for (int n = 0; n < 256; n++)
            acc = fmaf(arow[n0 + n], h2[(size_t)(n0 + n) * H_ + h], acc);
        part[sec][h] = acc;
    }
    __syncthreads();
    if (t < H_) rs[t] = part[0][t] + part[1][t] + part[2][t] + part[3][t];
    __syncthreads();

    {   // s = relu(r @ W2 + b2)   [H_]
        const int h = t & (H_ - 1);
        const int sec = t >> 8;
        float a2 = 0.f;
        const int k0 = sec * 64;
#pragma unroll 4
        for (int k = 0; k < 64; k++)
            a2 = fmaf(rs[k0 + k], W2[(k0 + k) * H_ + h], a2);
        part[sec][h] = a2;
    }
    __syncthreads();
    if (t < H_)
        ss[t] = fmaxf(part[0][t] + part[1][t] + part[2][t] + part[3][t] + b2[t], 0.f);
    __syncthreads();

    {   // out = s @ Wl + bl   [F_]
        const int h = t & (F_ - 1);
        const int sec = t >> 7;
        float a3 = 0.f;
        const int k0 = sec * 32;
#pragma unroll 4
        for (int k = 0; k < 32; k++)
            a3 = fmaf(ss[k0 + k], Wl[(k0 + k) * F_ + h], a3);
        partl[sec][h] = a3;
    }
    __syncthreads();
    if (t < F_) {
        float a = bl[t];
#pragma unroll
        for (int s = 0; s < 8; s++) a += partl[s][t];
        out[b * F_ + t] = a;
    }
}

// ---------------- launch ----------------
template <int CVT_A, int PREROUND>
static void launch_gemm(const float* A, const float* Bm, float* C,
                        int gridN, int gridM, int batch, int K, int ldb,
                        long sA, long sB, long sC, const float* bias, int relu)
{
    const int smem = 81920;
    cudaFuncSetAttribute(gemm_mma<CVT_A, PREROUND>,
                         cudaFuncAttributeMaxDynamicSharedMemorySize, smem);
    gemm_mma<CVT_A, PREROUND><<<dim3(gridN, gridM, batch), 128, smem>>>(
        A, Bm, C, K, K / 32, ldb, sA, sB, sC, bias, relu);
}

extern "C" void kernel_launch(void* const* d_in, const int* in_sizes, int n_in,
                              void* d_out, int out_size)
{
    const float* embs = (const float*)d_in[0];
    const float* adj  = (const float*)d_in[1];
    const float* W0   = (const float*)d_in[2];
    const float* b0   = (const float*)d_in[3];
    const float* W1   = (const float*)d_in[4];
    const float* b1   = (const float*)d_in[5];
    const float* W2   = (const float*)d_in[6];
    const float* b2   = (const float*)d_in[7];
    const float* Wl   = (const float*)d_in[8];
    const float* bl   = (const float*)d_in[9];
    float* out = (float*)d_out;

    float *T1, *T2, *hid2;
    cudaGetSymbolAddress((void**)&T1, g_T1);
    cudaGetSymbolAddress((void**)&T2, g_T2);
    cudaGetSymbolAddress((void**)&hid2, g_hid2);

    // L0A: T1 = adj @ embs            per graph [1024x1024]@[1024x128]
    launch_gemm<1, 1>(adj, embs, T1, 1, 8, B_, N_, F_,
                      (long)N_ * N_, (long)N_ * F_, (long)N_ * F_, nullptr, 0);
    // mid (fused L0B+L1A): T2 = relu(T1@W0+b0) @ W1
    {
        const int smem = 229376;  // 128K hid1s + 64K B stages + 32K A stages
        cudaFuncSetAttribute(mid_kernel,
                             cudaFuncAttributeMaxDynamicSharedMemorySize, smem);
        mid_kernel<<<512, 256, smem>>>(T1, W0, b0, W1, T2);
    }
    // L1B: hid2 = relu(adj @ T2 + b1) per graph [1024x1024]@[1024x256]
    launch_gemm<1, 0>(adj, T2, hid2, 2, 8, B_, N_, H_,
                      (long)N_ * N_, (long)N_ * H_, (long)N_ * H_, b1, 1);
    // L2 (node-0 slice) + linear head
    tail_kernel<<<B_, 1024>>>(adj, hid2, W2, b2, Wl, bl, out);
}

// round 9
// speedup vs baseline: 1.0222x; 1.0222x over previous
#include <cuda_runtime.h>
#include <cstdint>

#define B_ 64
#define N_ 1024
#define F_ 128
#define H_ 256

// Scratch (allocation-free rule: __device__ globals)
__device__ float g_T1[B_ * N_ * F_];            // adj @ embs        [B,N,F]  (tf32-rounded)
__device__ float g_hid1[(size_t)B_ * N_ * H_];  // relu(T1@W0+b0)    [B,N,H]  (tf32-rounded)
__device__ float g_T2[(size_t)B_ * N_ * H_];    // hid1 @ W1         [B,N,H]
__device__ float g_hid2[(size_t)B_ * N_ * H_];  // relu(adj@T2+b1)   [B,N,H]
__device__ float g_part[B_ * 8 * H_];           // tail partial dots [B,8,H]

__device__ __forceinline__ uint32_t s2u(const void* p) {
    uint32_t a;
    asm("{ .reg .u64 t; cvta.to.shared.u64 t, %1; cvt.u32.u64 %0, t; }" : "=r"(a) : "l"(p));
    return a;
}
__device__ __forceinline__ uint32_t f2tf(float f) {
    uint32_t r;
    asm("cvt.rna.tf32.f32 %0, %1;" : "=r"(r) : "f"(f));
    return r;
}
__device__ __forceinline__ uint32_t cvt_inplace(uint32_t x) {
    uint32_t r;
    asm("cvt.rna.tf32.f32 %0, %1;" : "=r"(r) : "f"(__uint_as_float(x)));
    return r;
}
__device__ __forceinline__ void ldsm4(uint32_t* r, uint32_t addr) {
    asm volatile("ldmatrix.sync.aligned.m8n8.x4.shared.b16 {%0,%1,%2,%3}, [%4];"
                 : "=r"(r[0]), "=r"(r[1]), "=r"(r[2]), "=r"(r[3]) : "r"(addr));
}
__device__ __forceinline__ void mma_tf32(float* d, const uint32_t* a, const uint32_t* b) {
    asm volatile(
        "mma.sync.aligned.m16n8k8.row.col.f32.tf32.tf32.f32 "
        "{%0,%1,%2,%3}, {%4,%5,%6,%7}, {%8,%9}, {%0,%1,%2,%3};"
        : "+f"(d[0]), "+f"(d[1]), "+f"(d[2]), "+f"(d[3])
        : "r"(a[0]), "r"(a[1]), "r"(a[2]), "r"(a[3]), "r"(b[0]), "r"(b[1]));
}
__device__ __forceinline__ void cpasync16(uint32_t dst, const void* src) {
    asm volatile("cp.async.cg.shared.global [%0], [%1], 16;" :: "r"(dst), "l"(src));
}
__device__ __forceinline__ void cp_commit() { asm volatile("cp.async.commit_group;"); }

// ---------------------------------------------------------------------------
// R7 GEMM (proven, unchanged): C[M,N] = A[M,K] @ B[K,N], CTA 128x128x32,
// 128 thr, 2x2 warps, warp 64x64, frag double-buffered, 3-stage cp.async A,
// 2-stage transpose-on-load B.
// ---------------------------------------------------------------------------
template <int CVT_A, int PREROUND>
__global__ __launch_bounds__(128)
void gemm_mma(const float* __restrict__ Ag, const float* __restrict__ Bg,
              float* __restrict__ Cg, int K, int nk, int ldb,
              long sA, long sB, long sC,
              const float* __restrict__ bias, int relu)
{
    extern __shared__ float smp[];
    const uint32_t smb = s2u(smp);
    const int tid = threadIdx.x;
    const int lid = tid & 31;
    const int wid = tid >> 5;
    const int mw = wid >> 1;
    const int nw = wid & 1;

    const float* A = Ag + (size_t)blockIdx.z * sA + (size_t)blockIdx.y * 128 * K;
    const float* Bp = Bg + (size_t)blockIdx.z * sB + blockIdx.x * 128 + tid;
    float* C = Cg + (size_t)blockIdx.z * sC + (size_t)blockIdx.y * 128 * ldb + blockIdx.x * 128;
    if (bias) bias += blockIdx.x * 128;

    const int a_row_l = tid >> 3;
    const int a_f4 = tid & 7;
    auto issueA = [&](int kt, int st) {
        const uint32_t dstb = smb + st * 16384;
        const float* src = A + (size_t)kt * 32 + a_f4 * 4;
#pragma unroll
        for (int j = 0; j < 8; j++) {
            int row = a_row_l + j * 16;
            uint32_t dst = dstb + row * 128 + ((a_f4 ^ (row & 7)) << 4);
            cpasync16(dst, src + (size_t)row * K);
        }
        cp_commit();
    };

    float bv[32];
    auto ldgB = [&](int kt) {
        const float* src = Bp + (size_t)kt * 32 * ldb;
#pragma unroll
        for (int k = 0; k < 32; k++) bv[k] = src[(size_t)k * ldb];
    };
    const uint32_t b_row128 = tid * 128;
    const int b_n7 = tid & 7;
    auto stsB = [&](int st) {
        char* base = (char*)smp + 49152 + st * 16384 + b_row128;
#pragma unroll
        for (int k4 = 0; k4 < 8; k4++) {
            uint4 w;
            w.x = f2tf(bv[4 * k4 + 0]);
            w.y = f2tf(bv[4 * k4 + 1]);
            w.z = f2tf(bv[4 * k4 + 2]);
            w.w = f2tf(bv[4 * k4 + 3]);
            *(uint4*)(base + ((k4 ^ b_n7) << 4)) = w;
        }
    };

    int aR128[4], aR7[4];
    const int l4a = (lid >> 4) & 1;
#pragma unroll
    for (int mf = 0; mf < 4; mf++) {
        int r = mw * 64 + mf * 16 + (lid & 7) + 8 * ((lid >> 3) & 1);
        aR128[mf] = r * 128;
        aR7[mf] = r & 7;
    }
    int bN128[4], bN7[4];
    const int l4b = (lid >> 3) & 1;
#pragma unroll
    for (int p = 0; p < 4; p++) {
        int n = nw * 64 + p * 16 + (lid & 7) + 8 * ((lid >> 4) & 1);
        bN128[p] = n * 128;
        bN7[p] = n & 7;
    }

    float acc[4][8][4];
#pragma unroll
    for (int mf = 0; mf < 4; mf++)
#pragma unroll
        for (int nf = 0; nf < 8; nf++)
#pragma unroll
            for (int e = 0; e < 4; e++) acc[mf][nf][e] = 0.f;

    issueA(0, 0);
    issueA(1, 1);
    ldgB(0);
    stsB(0);
    asm volatile("cp.async.wait_group 1;");
    __syncthreads();

    int sa = 0;
    for (int t = 0; t < nk; t++) {
        if (t + 2 < nk) issueA(t + 2, (t + 2) % 3);
        if (t + 1 < nk) ldgB(t + 1);

        const uint32_t Ab = smb + sa * 16384;
        const uint32_t Bb = smb + 49152 + (t & 1) * 16384;

        uint32_t a[2][4][4], b[2][8][2];
        auto ldfr = [&](int kb, int pb) {
#pragma unroll
            for (int mf = 0; mf < 4; mf++) {
                ldsm4(a[pb][mf], Ab + aR128[mf] + ((((kb << 1) | l4a) ^ aR7[mf]) << 4));
                if (CVT_A) {
                    a[pb][mf][0] = cvt_inplace(a[pb][mf][0]);
                    a[pb][mf][1] = cvt_inplace(a[pb][mf][1]);
                    a[pb][mf][2] = cvt_inplace(a[pb][mf][2]);
                    a[pb][mf][3] = cvt_inplace(a[pb][mf][3]);
                }
            }
#pragma unroll
            for (int p = 0; p < 4; p++) {
                uint32_t r[4];
                ldsm4(r, Bb + bN128[p] + ((((kb << 1) | l4b) ^ bN7[p]) << 4));
                b[pb][2 * p][0] = r[0]; b[pb][2 * p][1] = r[1];
                b[pb][2 * p + 1][0] = r[2]; b[pb][2 * p + 1][1] = r[3];
            }
        };

        ldfr(0, 0);
#pragma unroll
        for (int kb = 0; kb < 4; kb++) {
            if (kb < 3) ldfr(kb + 1, (kb + 1) & 1);
            const int pb = kb & 1;
#pragma unroll
            for (int mf = 0; mf < 4; mf++)
#pragma unroll
                for (int nf = 0; nf < 8; nf++)
                    mma_tf32(acc[mf][nf], a[pb][mf], b[pb][nf]);
        }

        if (t + 1 < nk) {
            stsB((t + 1) & 1);
            if (t + 2 < nk) asm volatile("cp.async.wait_group 1;");
            else            asm volatile("cp.async.wait_group 0;");
        }
        __syncthreads();
        sa = (sa + 1 == 3) ? 0 : sa + 1;
    }

    const int r0 = mw * 64 + (lid >> 2);
    const int c0 = nw * 64 + (lid & 3) * 2;
#pragma unroll
    for (int mf = 0; mf < 4; mf++) {
        const int row = r0 + mf * 16;
#pragma unroll
        for (int nf = 0; nf < 8; nf++) {
            const int col = c0 + nf * 8;
            float2 v0 = make_float2(acc[mf][nf][0], acc[mf][nf][1]);
            float2 v1 = make_float2(acc[mf][nf][2], acc[mf][nf][3]);
            if (bias) {
                float bx = bias[col], by = bias[col + 1];
                v0.x += bx; v0.y += by; v1.x += bx; v1.y += by;
            }
            if (relu) {
                v0.x = fmaxf(v0.x, 0.f); v0.y = fmaxf(v0.y, 0.f);
                v1.x = fmaxf(v1.x, 0.f); v1.y = fmaxf(v1.y, 0.f);
            }
            if (PREROUND) {
                v0.x = __uint_as_float(f2tf(v0.x)); v0.y = __uint_as_float(f2tf(v0.y));
                v1.x = __uint_as_float(f2tf(v1.x)); v1.y = __uint_as_float(f2tf(v1.y));
            }
            *(float2*)(C + (size_t)row * ldb + col) = v0;
            *(float2*)(C + (size_t)(row + 8) * ldb + col) = v1;
        }
    }
}

// ---------------------------------------------------------------------------
// tail1: partial dot over a 128-node slice.
// part[b][s][h] = sum_{n in slice s} adj[b,0,n] * hid2[b,n,h]
// grid (8, 64) = 512 CTAs -> full chip; hid2 reads perfectly coalesced.
// ---------------------------------------------------------------------------
__global__ __launch_bounds__(256)
void tail1_kernel(const float* __restrict__ adj, const float* __restrict__ hid2,
                  float* __restrict__ part)
{
    const int s = blockIdx.x;   // 0..7
    const int b = blockIdx.y;   // 0..63
    const int h = threadIdx.x;  // 0..255
    __shared__ float arow[128];

    const float* ar = adj + (size_t)b * N_ * N_ + s * 128;  // row 0 of graph b, slice s
    if (h < 128) arow[h] = ar[h];
    __syncthreads();

    const float* h2 = hid2 + (size_t)b * N_ * H_ + (size_t)s * 128 * H_ + h;
    float acc = 0.f;
#pragma unroll 8
    for (int n = 0; n < 128; n++)
        acc = fmaf(arow[n], h2[(size_t)n * H_], acc);
    part[(b * 8 + s) * H_ + h] = acc;
}

// ---------------------------------------------------------------------------
// tail2: reduce partials, then r@W2 (relu) and @Wl head.  grid 64, block 256.
// ---------------------------------------------------------------------------
__global__ __launch_bounds__(256)
void tail2_kernel(const float* __restrict__ part,
                  const float* __restrict__ W2, const float* __restrict__ b2,
                  const float* __restrict__ Wl, const float* __restrict__ bl,
                  float* __restrict__ out)
{
    const int b = blockIdx.x;
    const int t = threadIdx.x;  // 256
    __shared__ float rs[H_];
    __shared__ float ss[H_];

    {   // rs = sum of 8 slice partials (fixed order)
        const float* p = part + b * 8 * H_ + t;
        float a = p[0];
#pragma unroll
        for (int s = 1; s < 8; s++) a += p[s * H_];
        rs[t] = a;
    }
    __syncthreads();

    {   // ss = relu(rs @ W2 + b2)
        float a2 = b2[t];
#pragma unroll 8
        for (int k = 0; k < H_; k++)
            a2 = fmaf(rs[k], W2[k * H_ + t], a2);
        ss[t] = fmaxf(a2, 0.f);
    }
    __syncthreads();

    if (t < F_) {   // out = ss @ Wl + bl
        float a3 = bl[t];
#pragma unroll 8
        for (int k = 0; k < H_; k++)
            a3 = fmaf(ss[k], Wl[k * F_ + t], a3);
        out[b * F_ + t] = a3;
    }
}

// ---------------- launch ----------------
template <int CVT_A, int PREROUND>
static void launch_gemm(const float* A, const float* Bm, float* C,
                        int gridN, int gridM, int batch, int K, int ldb,
                        long sA, long sB, long sC, const float* bias, int relu)
{
    const int smem = 81920;
    cudaFuncSetAttribute(gemm_mma<CVT_A, PREROUND>,
                         cudaFuncAttributeMaxDynamicSharedMemorySize, smem);
    gemm_mma<CVT_A, PREROUND><<<dim3(gridN, gridM, batch), 128, smem>>>(
        A, Bm, C, K, K / 32, ldb, sA, sB, sC, bias, relu);
}

extern "C" void kernel_launch(void* const* d_in, const int* in_sizes, int n_in,
                              void* d_out, int out_size)
{
    const float* embs = (const float*)d_in[0];
    const float* adj  = (const float*)d_in[1];
    const float* W0   = (const float*)d_in[2];
    const float* b0   = (const float*)d_in[3];
    const float* W1   = (const float*)d_in[4];
    const float* b1   = (const float*)d_in[5];
    const float* W2   = (const float*)d_in[6];
    const float* b2   = (const float*)d_in[7];
    const float* Wl   = (const float*)d_in[8];
    const float* bl   = (const float*)d_in[9];
    float* out = (float*)d_out;

    float *T1, *hid1, *T2, *hid2, *part;
    cudaGetSymbolAddress((void**)&T1, g_T1);
    cudaGetSymbolAddress((void**)&hid1, g_hid1);
    cudaGetSymbolAddress((void**)&T2, g_T2);
    cudaGetSymbolAddress((void**)&hid2, g_hid2);
    cudaGetSymbolAddress((void**)&part, g_part);

    // L0A: T1 = adj @ embs            per graph [1024x1024]@[1024x128]
    launch_gemm<1, 1>(adj, embs, T1, 1, 8, B_, N_, F_,
                      (long)N_ * N_, (long)N_ * F_, (long)N_ * F_, nullptr, 0);
    // L0B: hid1 = relu(T1 @ W0 + b0)  [65536x128]@[128x256]
    launch_gemm<0, 1>(T1, W0, hid1, 2, 512, 1, F_, H_, 0, 0, 0, b0, 1);
    // L1A: T2 = hid1 @ W1             [65536x256]@[256x256]
    launch_gemm<0, 0>(hid1, W1, T2, 2, 512, 1, H_, H_, 0, 0, 0, nullptr, 0);
    // L1B: hid2 = relu(adj @ T2 + b1) per graph [1024x1024]@[1024x256]
    launch_gemm<1, 0>(adj, T2, hid2, 2, 8, B_, N_, H_,
                      (long)N_ * N_, (long)N_ * H_, (long)N_ * H_, b1, 1);
    // tail: L2 (node-0 slice) + linear head, split for full-chip parallelism
    tail1_kernel<<<dim3(8, B_), 256>>>(adj, hid2, part);
    tail2_kernel<<<B_, 256>>>(part, W2, b2, Wl, bl, out);
}

// round 10
// speedup vs baseline: 1.1061x; 1.0821x over previous
#include <cuda_runtime.h>
#include <cstdint>

#define B_ 64
#define N_ 1024
#define F_ 128
#define H_ 256

// Scratch (allocation-free rule: __device__ globals)
__device__ float g_T1[B_ * N_ * F_];            // adj @ embs        [B,N,F]  (tf32-rounded)
__device__ float g_hid1[(size_t)B_ * N_ * H_];  // relu(T1@W0+b0)    [B,N,H]  (tf32-rounded)
__device__ float g_T2[(size_t)B_ * N_ * H_];    // hid1 @ W1         [B,N,H]
__device__ float g_hid2[(size_t)B_ * N_ * H_];  // relu(adj@T2+b1)   [B,N,H]
__device__ float g_part[B_ * 8 * H_];           // tail partial dots [B,8,H]

__device__ __forceinline__ uint32_t s2u(const void* p) {
    uint32_t a;
    asm("{ .reg .u64 t; cvta.to.shared.u64 t, %1; cvt.u32.u64 %0, t; }" : "=r"(a) : "l"(p));
    return a;
}
__device__ __forceinline__ uint32_t f2tf(float f) {
    uint32_t r;
    asm("cvt.rna.tf32.f32 %0, %1;" : "=r"(r) : "f"(f));
    return r;
}
__device__ __forceinline__ void ldsm4(uint32_t* r, uint32_t addr) {
    asm volatile("ldmatrix.sync.aligned.m8n8.x4.shared.b16 {%0,%1,%2,%3}, [%4];"
                 : "=r"(r[0]), "=r"(r[1]), "=r"(r[2]), "=r"(r[3]) : "r"(addr));
}
__device__ __forceinline__ void mma_tf32(float* d, const uint32_t* a, const uint32_t* b) {
    asm volatile(
        "mma.sync.aligned.m16n8k8.row.col.f32.tf32.tf32.f32 "
        "{%0,%1,%2,%3}, {%4,%5,%6,%7}, {%8,%9}, {%0,%1,%2,%3};"
        : "+f"(d[0]), "+f"(d[1]), "+f"(d[2]), "+f"(d[3])
        : "r"(a[0]), "r"(a[1]), "r"(a[2]), "r"(a[3]), "r"(b[0]), "r"(b[1]));
}
__device__ __forceinline__ void cpasync16(uint32_t dst, const void* src) {
    asm volatile("cp.async.cg.shared.global [%0], [%1], 16;" :: "r"(dst), "l"(src));
}
__device__ __forceinline__ void cp_commit() { asm volatile("cp.async.commit_group;"); }

// ---------------------------------------------------------------------------
// GEMM: C[M,N] = A[M,K] @ B[K,N], CTA 128x128x32, 128 thr, 2x2 warps,
// warp 64x64, frag double-buffered, 3-stage cp.async A, 2-stage B.
// A operand is fed to mma as raw fp32 bits when not pre-rounded: the tf32
// mma reads the register as tf32 (HW truncation of low mantissa bits), so
// no cvt is needed on the consumer path at all.
// PREROUND: round C to tf32 (rna) before store.
// ---------------------------------------------------------------------------
template <int PREROUND>
__global__ __launch_bounds__(128)
void gemm_mma(const float* __restrict__ Ag, const float* __restrict__ Bg,
              float* __restrict__ Cg, int K, int nk, int ldb,
              long sA, long sB, long sC,
              const float* __restrict__ bias, int relu)
{
    extern __shared__ float smp[];
    const uint32_t smb = s2u(smp);
    const int tid = threadIdx.x;
    const int lid = tid & 31;
    const int wid = tid >> 5;
    const int mw = wid >> 1;
    const int nw = wid & 1;

    const float* A = Ag + (size_t)blockIdx.z * sA + (size_t)blockIdx.y * 128 * K;
    const float* Bp = Bg + (size_t)blockIdx.z * sB + blockIdx.x * 128 + tid;
    float* C = Cg + (size_t)blockIdx.z * sC + (size_t)blockIdx.y * 128 * ldb + blockIdx.x * 128;
    if (bias) bias += blockIdx.x * 128;

    const int a_row_l = tid >> 3;
    const int a_f4 = tid & 7;
    auto issueA = [&](int kt, int st) {
        const uint32_t dstb = smb + st * 16384;
        const float* src = A + (size_t)kt * 32 + a_f4 * 4;
#pragma unroll
        for (int j = 0; j < 8; j++) {
            int row = a_row_l + j * 16;
            uint32_t dst = dstb + row * 128 + ((a_f4 ^ (row & 7)) << 4);
            cpasync16(dst, src + (size_t)row * K);
        }
        cp_commit();
    };

    float bv[32];
    auto ldgB = [&](int kt) {
        const float* src = Bp + (size_t)kt * 32 * ldb;
#pragma unroll
        for (int k = 0; k < 32; k++) bv[k] = src[(size_t)k * ldb];
    };
    const uint32_t b_row128 = tid * 128;
    const int b_n7 = tid & 7;
    auto stsB = [&](int st) {
        char* base = (char*)smp + 49152 + st * 16384 + b_row128;
#pragma unroll
        for (int k4 = 0; k4 < 8; k4++) {
            uint4 w;
            w.x = f2tf(bv[4 * k4 + 0]);
            w.y = f2tf(bv[4 * k4 + 1]);
            w.z = f2tf(bv[4 * k4 + 2]);
            w.w = f2tf(bv[4 * k4 + 3]);
            *(uint4*)(base + ((k4 ^ b_n7) << 4)) = w;
        }
    };

    int aR128[4], aR7[4];
    const int l4a = (lid >> 4) & 1;
#pragma unroll
    for (int mf = 0; mf < 4; mf++) {
        int r = mw * 64 + mf * 16 + (lid & 7) + 8 * ((lid >> 3) & 1);
        aR128[mf] = r * 128;
        aR7[mf] = r & 7;
    }
    int bN128[4], bN7[4];
    const int l4b = (lid >> 3) & 1;
#pragma unroll
    for (int p = 0; p < 4; p++) {
        int n = nw * 64 + p * 16 + (lid & 7) + 8 * ((lid >> 4) & 1);
        bN128[p] = n * 128;
        bN7[p] = n & 7;
    }

    float acc[4][8][4];
#pragma unroll
    for (int mf = 0; mf < 4; mf++)
#pragma unroll
        for (int nf = 0; nf < 8; nf++)
#pragma unroll
            for (int e = 0; e < 4; e++) acc[mf][nf][e] = 0.f;

    issueA(0, 0);
    issueA(1, 1);
    ldgB(0);
    stsB(0);
    asm volatile("cp.async.wait_group 1;");
    __syncthreads();

    int sa = 0;
    for (int t = 0; t < nk; t++) {
        if (t + 2 < nk) issueA(t + 2, (t + 2) % 3);
        if (t + 1 < nk) ldgB(t + 1);

        const uint32_t Ab = smb + sa * 16384;
        const uint32_t Bb = smb + 49152 + (t & 1) * 16384;

        uint32_t a[2][4][4], b[2][8][2];
        auto ldfr = [&](int kb, int pb) {
#pragma unroll
            for (int mf = 0; mf < 4; mf++)
                ldsm4(a[pb][mf], Ab + aR128[mf] + ((((kb << 1) | l4a) ^ aR7[mf]) << 4));
#pragma unroll
            for (int p = 0; p < 4; p++) {
                uint32_t r[4];
                ldsm4(r, Bb + bN128[p] + ((((kb << 1) | l4b) ^ bN7[p]) << 4));
                b[pb][2 * p][0] = r[0]; b[pb][2 * p][1] = r[1];
                b[pb][2 * p + 1][0] = r[2]; b[pb][2 * p + 1][1] = r[3];
            }
        };

        ldfr(0, 0);
#pragma unroll
        for (int kb = 0; kb < 4; kb++) {
            if (kb < 3) ldfr(kb + 1, (kb + 1) & 1);
            const int pb = kb & 1;
#pragma unroll
            for (int mf = 0; mf < 4; mf++)
#pragma unroll
                for (int nf = 0; nf < 8; nf++)
                    mma_tf32(acc[mf][nf], a[pb][mf], b[pb][nf]);
        }

        if (t + 1 < nk) {
            stsB((t + 1) & 1);
            if (t + 2 < nk) asm volatile("cp.async.wait_group 1;");
            else            asm volatile("cp.async.wait_group 0;");
        }
        __syncthreads();
        sa = (sa + 1 == 3) ? 0 : sa + 1;
    }

    const int r0 = mw * 64 + (lid >> 2);
    const int c0 = nw * 64 + (lid & 3) * 2;
#pragma unroll
    for (int mf = 0; mf < 4; mf++) {
        const int row = r0 + mf * 16;
#pragma unroll
        for (int nf = 0; nf < 8; nf++) {
            const int col = c0 + nf * 8;
            float2 v0 = make_float2(acc[mf][nf][0], acc[mf][nf][1]);
            float2 v1 = make_float2(acc[mf][nf][2], acc[mf][nf][3]);
            if (bias) {
                float bx = bias[col], by = bias[col + 1];
                v0.x += bx; v0.y += by; v1.x += bx; v1.y += by;
            }
            if (relu) {
                v0.x = fmaxf(v0.x, 0.f); v0.y = fmaxf(v0.y, 0.f);
                v1.x = fmaxf(v1.x, 0.f); v1.y = fmaxf(v1.y, 0.f);
            }
            if (PREROUND) {
                v0.x = __uint_as_float(f2tf(v0.x)); v0.y = __uint_as_float(f2tf(v0.y));
                v1.x = __uint_as_float(f2tf(v1.x)); v1.y = __uint_as_float(f2tf(v1.y));
            }
            *(float2*)(C + (size_t)row * ldb + col) = v0;
            *(float2*)(C + (size_t)(row + 8) * ldb + col) = v1;
        }
    }
}

// ---------------------------------------------------------------------------
// tail1: partial dot over a 128-node slice.
// part[b][s][h] = sum_{n in slice s} adj[b,0,n] * hid2[b,n,h]
// ---------------------------------------------------------------------------
__global__ __launch_bounds__(256)
void tail1_kernel(const float* __restrict__ adj, const float* __restrict__ hid2,
                  float* __restrict__ part)
{
    const int s = blockIdx.x;   // 0..7
    const int b = blockIdx.y;   // 0..63
    const int h = threadIdx.x;  // 0..255
    __shared__ float arow[128];

    const float* ar = adj + (size_t)b * N_ * N_ + s * 128;
    if (h < 128) arow[h] = ar[h];
    __syncthreads();

    const float* h2 = hid2 + (size_t)b * N_ * H_ + (size_t)s * 128 * H_ + h;
    float acc = 0.f;
#pragma unroll 8
    for (int n = 0; n < 128; n++)
        acc = fmaf(arow[n], h2[(size_t)n * H_], acc);
    part[(b * 8 + s) * H_ + h] = acc;
}

// ---------------------------------------------------------------------------
// tail2: reduce partials, then r@W2 (relu) and @Wl head.  grid 64, block 256.
// ---------------------------------------------------------------------------
__global__ __launch_bounds__(256)
void tail2_kernel(const float* __restrict__ part,
                  const float* __restrict__ W2, const float* __restrict__ b2,
                  const float* __restrict__ Wl, const float* __restrict__ bl,
                  float* __restrict__ out)
{
    const int b = blockIdx.x;
    const int t = threadIdx.x;  // 256
    __shared__ float rs[H_];
    __shared__ float ss[H_];

    {
        const float* p = part + b * 8 * H_ + t;
        float a = p[0];
#pragma unroll
        for (int s = 1; s < 8; s++) a += p[s * H_];
        rs[t] = a;
    }
    __syncthreads();

    {
        float a2 = b2[t];
#pragma unroll 8
        for (int k = 0; k < H_; k++)
            a2 = fmaf(rs[k], W2[k * H_ + t], a2);
        ss[t] = fmaxf(a2, 0.f);
    }
    __syncthreads();

    if (t < F_) {
        float a3 = bl[t];
#pragma unroll 8
        for (int k = 0; k < H_; k++)
            a3 = fmaf(ss[k], Wl[k * F_ + t], a3);
        out[b * F_ + t] = a3;
    }
}

// ---------------- launch ----------------
template <int PREROUND>
static void launch_gemm(const float* A, const float* Bm, float* C,
                        int gridN, int gridM, int batch, int K, int ldb,
                        long sA, long sB, long sC, const float* bias, int relu)
{
    const int smem = 81920;
    cudaFuncSetAttribute(gemm_mma<PREROUND>,
                         cudaFuncAttributeMaxDynamicSharedMemorySize, smem);
    gemm_mma<PREROUND><<<dim3(gridN, gridM, batch), 128, smem>>>(
        A, Bm, C, K, K / 32, ldb, sA, sB, sC, bias, relu);
}

extern "C" void kernel_launch(void* const* d_in, const int* in_sizes, int n_in,
                              void* d_out, int out_size)
{
    const float* embs = (const float*)d_in[0];
    const float* adj  = (const float*)d_in[1];
    const float* W0   = (const float*)d_in[2];
    const float* b0   = (const float*)d_in[3];
    const float* W1   = (const float*)d_in[4];
    const float* b1   = (const float*)d_in[5];
    const float* W2   = (const float*)d_in[6];
    const float* b2   = (const float*)d_in[7];
    const float* Wl   = (const float*)d_in[8];
    const float* bl   = (const float*)d_in[9];
    float* out = (float*)d_out;

    float *T1, *hid1, *T2, *hid2, *part;
    cudaGetSymbolAddress((void**)&T1, g_T1);
    cudaGetSymbolAddress((void**)&hid1, g_hid1);
    cudaGetSymbolAddress((void**)&T2, g_T2);
    cudaGetSymbolAddress((void**)&hid2, g_hid2);
    cudaGetSymbolAddress((void**)&part, g_part);

    // L0A: T1 = adj @ embs            per graph [1024x1024]@[1024x128]
    launch_gemm<1>(adj, embs, T1, 1, 8, B_, N_, F_,
                   (long)N_ * N_, (long)N_ * F_, (long)N_ * F_, nullptr, 0);
    // L0B: hid1 = relu(T1 @ W0 + b0)  [65536x128]@[128x256]
    launch_gemm<1>(T1, W0, hid1, 2, 512, 1, F_, H_, 0, 0, 0, b0, 1);
    // L1A: T2 = hid1 @ W1             [65536x256]@[256x256]
    launch_gemm<0>(hid1, W1, T2, 2, 512, 1, H_, H_, 0, 0, 0, nullptr, 0);
    // L1B: hid2 = relu(adj @ T2 + b1) per graph [1024x1024]@[1024x256]
    launch_gemm<0>(adj, T2, hid2, 2, 8, B_, N_, H_,
                   (long)N_ * N_, (long)N_ * H_, (long)N_ * H_, b1, 1);
    // tail: L2 (node-0 slice) + linear head
    tail1_kernel<<<dim3(8, B_), 256>>>(adj, hid2, part);
    tail2_kernel<<<B_, 256>>>(part, W2, b2, Wl, bl, out);
}